// round 5
// baseline (speedup 1.0000x reference)
#include <cuda_runtime.h>
#include <math.h>

// ---------------- scratch (device globals: allocation-free) ------------------
__device__ float g_A [16*64*128*128];   // 67 MB
__device__ float g_B [16*128*64*64];    // 33.5 MB
__device__ float g_B2[16*128*64*64];    // 33.5 MB
__device__ float g_C [16*128*64*64];    // 33.5 MB
__device__ float g_D [16*32*64*64];     // 8.4 MB
__device__ float g_E [16*64*64*64];     // 16.8 MB (z_e)
__device__ float g_F [16*64*64*64];     // 16.8 MB (z_q)
__device__ float g_part[1024];

// ---------------- generic direct conv ----------------------------------------
// thread: 4 out-x  x 8 out-channels. block 128 = 16 px-groups x 8 rows.
template<int K, int STRIDE, bool RELU_IN, bool TRANSPOSED>
__global__ void __launch_bounds__(128) conv_fwd(
    const float* __restrict__ in, const float* __restrict__ w,
    const float* __restrict__ bias, const float* __restrict__ resid,
    float* __restrict__ out,
    int CIN, int COUT, int H, int W, int OH, int OW, int PAD, int cgroups,
    int relu_out)
{
    constexpr int KK = K * K;
    constexpr int CICH = (K == 4) ? 64 : 128;
    __shared__ float sw[8 * CICH * KK];

    int t   = threadIdx.x;
    int tx  = t & 15, ty = t >> 4;
    int ox0 = blockIdx.x * 64 + tx * 4;
    int oy  = blockIdx.y * 8 + ty;
    int n   = blockIdx.z / cgroups;
    int co0 = (blockIdx.z % cgroups) * 8;

    float acc[8][4];
#pragma unroll
    for (int c = 0; c < 8; c++)
#pragma unroll
        for (int p = 0; p < 4; p++) acc[c][p] = 0.f;

    for (int ci0 = 0; ci0 < CIN; ci0 += CICH) {
        int cich = min(CICH, CIN - ci0);
        int nw = 8 * cich * KK;
        for (int i = t; i < nw; i += 128) {
            int c  = i / (cich * KK);
            int r  = i - c * cich * KK;
            int ci = r / KK;
            int kk = r - ci * KK;
            int ky = kk / K, kx = kk - ky * K;
            int co = co0 + c;
            float v = 0.f;
            if (co < COUT) {
                if (TRANSPOSED)
                    v = w[(((ci0 + ci) * COUT + co) * K + (K - 1 - ky)) * K + (K - 1 - kx)];
                else
                    v = w[((co * CIN + (ci0 + ci)) * K + ky) * K + kx];
            }
            sw[i] = v;
        }
        __syncthreads();

        const float* inb = in + (n * CIN + ci0) * H * W;
        for (int ci = 0; ci < cich; ci++) {
            const float* inc = inb + ci * H * W;
#pragma unroll
            for (int ky = 0; ky < K; ky++) {
                int iy = oy * STRIDE - PAD + ky;
                if ((unsigned)iy >= (unsigned)H) continue;
                const float* rowp = inc + iy * W;
#pragma unroll
                for (int kx = 0; kx < K; kx++) {
                    float iv[4];
#pragma unroll
                    for (int p = 0; p < 4; p++) {
                        int ix = (ox0 + p) * STRIDE - PAD + kx;
                        float v = ((unsigned)ix < (unsigned)W) ? __ldg(rowp + ix) : 0.f;
                        if (RELU_IN) v = fmaxf(v, 0.f);
                        iv[p] = v;
                    }
                    const float* wp = sw + ci * KK + ky * K + kx;
#pragma unroll
                    for (int c = 0; c < 8; c++) {
                        float wv = wp[c * cich * KK];
#pragma unroll
                        for (int p = 0; p < 4; p++)
                            acc[c][p] = fmaf(iv[p], wv, acc[c][p]);
                    }
                }
            }
        }
        __syncthreads();
    }

#pragma unroll
    for (int c = 0; c < 8; c++) {
        int co = co0 + c;
        if (co >= COUT) break;
        float b = bias ? __ldg(bias + co) : 0.f;
        int ob = ((n * COUT + co) * OH + oy) * OW + ox0;
#pragma unroll
        for (int p = 0; p < 4; p++) {
            float v = acc[c][p] + b;
            if (resid) v += resid[ob + p];
            if (relu_out) v = fmaxf(v, 0.f);
            out[ob + p] = v;
        }
    }
}

// ---------------- transposed conv, stride 2, K=4, pad 1 ----------------------
// gather form: iy = (oy + 1 - ky)/2 when even. unflipped weight w[ci][co][ky][kx].
__global__ void __launch_bounds__(128) convt_s2(
    const float* __restrict__ in, const float* __restrict__ w,
    const float* __restrict__ bias, float* __restrict__ out,
    int CIN, int COUT, int H, int W, int cgroups, int relu_in, int relu_out)
{
    __shared__ float sw[8 * 64 * 16];
    int t = threadIdx.x;
    int tx = t & 15, tyv = t >> 4;
    int parity = blockIdx.x & 1;
    int xch    = blockIdx.x >> 1;
    int OH = 2 * H, OW = 2 * W;
    int ox0 = xch * 128 + 8 * tx + parity;    // this thread: ox0 + 2p, p=0..3
    int oy  = blockIdx.y * 8 + tyv;
    int n   = blockIdx.z / cgroups;
    int co0 = (blockIdx.z % cgroups) * 8;

    float acc[8][4];
#pragma unroll
    for (int c = 0; c < 8; c++)
#pragma unroll
        for (int p = 0; p < 4; p++) acc[c][p] = 0.f;

    for (int ci0 = 0; ci0 < CIN; ci0 += 64) {
        int cich = min(64, CIN - ci0);
        int nw = 8 * cich * 16;
        for (int i = t; i < nw; i += 128) {
            int c  = i / (cich * 16);
            int r  = i - c * cich * 16;
            int ci = r >> 4;
            int kk = r & 15;
            int co = co0 + c;
            sw[i] = (co < COUT) ? w[((ci0 + ci) * COUT + co) * 16 + kk] : 0.f;
        }
        __syncthreads();

        for (int ci = 0; ci < cich; ci++) {
            const float* inc = in + (n * CIN + ci0 + ci) * H * W;
#pragma unroll
            for (int ky = 0; ky < 4; ky++) {
                int t1 = oy + 1 - ky;
                if (t1 & 1) continue;
                int iy = t1 >> 1;
                if ((unsigned)iy >= (unsigned)H) continue;
                const float* rowp = inc + iy * W;
#pragma unroll
                for (int kx = 0; kx < 4; kx++) {
                    int t2 = ox0 + 1 - kx;
                    if (t2 & 1) continue;
                    int ixb = t2 >> 1;
                    float iv[4];
#pragma unroll
                    for (int p = 0; p < 4; p++) {
                        int ix = ixb + p;
                        float v = ((unsigned)ix < (unsigned)W) ? __ldg(rowp + ix) : 0.f;
                        if (relu_in) v = fmaxf(v, 0.f);
                        iv[p] = v;
                    }
                    const float* wp = sw + ci * 16 + ky * 4 + kx;
#pragma unroll
                    for (int c = 0; c < 8; c++) {
                        float wv = wp[c * cich * 16];
#pragma unroll
                        for (int p = 0; p < 4; p++)
                            acc[c][p] = fmaf(iv[p], wv, acc[c][p]);
                    }
                }
            }
        }
        __syncthreads();
    }

#pragma unroll
    for (int c = 0; c < 8; c++) {
        int co = co0 + c;
        if (co >= COUT) break;
        float b = bias ? __ldg(bias + co) : 0.f;
#pragma unroll
        for (int p = 0; p < 4; p++) {
            int ox = ox0 + 2 * p;
            int o = ((n * COUT + co) * OH + oy) * OW + ox;
            float v = acc[c][p] + b;
            if (relu_out) v = fmaxf(v, 0.f);
            out[o] = v;
        }
    }
}

// ---------------- fused decoder residual iteration ---------------------------
// x_out = x_in + W2 * relu(W1 (*) relu(x_in)), W1:[2,128,3,3], W2:[128,2,1,1]
__global__ void __launch_bounds__(128) decres_fused(
    const float* __restrict__ xin, const float* __restrict__ w1,
    const float* __restrict__ w2, float* __restrict__ xout)
{
    __shared__ float sw1[2 * 128 * 9];
    __shared__ float sw2[256];
    __shared__ float h_s[2][8][64];
    int t  = threadIdx.x;
    int by = blockIdx.x;            // 0..7 (8-row stripe)
    int n  = blockIdx.y;            // 0..15
    for (int i = t; i < 2304; i += 128) sw1[i] = w1[i];
    for (int i = t; i < 256;  i += 128) sw2[i] = w2[i];
    __syncthreads();

    int tx = t & 15, tyv = t >> 4;
    int ox0 = tx * 4;
    int oy  = by * 8 + tyv;
    float a0[4] = {0,0,0,0}, a1[4] = {0,0,0,0};
    const float* xb = xin + n * 128 * 4096;
    for (int ci = 0; ci < 128; ci++) {
        const float* inc = xb + ci * 4096;
#pragma unroll
        for (int ky = 0; ky < 3; ky++) {
            int iy = oy - 1 + ky;
            if ((unsigned)iy >= 64u) continue;
            const float* rowp = inc + iy * 64;
            float iv[6];
#pragma unroll
            for (int q = 0; q < 6; q++) {
                int ix = ox0 - 1 + q;
                float v = ((unsigned)ix < 64u) ? __ldg(rowp + ix) : 0.f;
                iv[q] = fmaxf(v, 0.f);
            }
            const float* w1p0 = sw1 + ci * 9 + ky * 3;
            const float* w1p1 = sw1 + (128 + ci) * 9 + ky * 3;
#pragma unroll
            for (int kx = 0; kx < 3; kx++) {
                float wv0 = w1p0[kx], wv1 = w1p1[kx];
#pragma unroll
                for (int p = 0; p < 4; p++) {
                    a0[p] = fmaf(iv[p + kx], wv0, a0[p]);
                    a1[p] = fmaf(iv[p + kx], wv1, a1[p]);
                }
            }
        }
    }
#pragma unroll
    for (int p = 0; p < 4; p++) {
        h_s[0][tyv][ox0 + p] = fmaxf(a0[p], 0.f);
        h_s[1][tyv][ox0 + p] = fmaxf(a1[p], 0.f);
    }
    __syncthreads();

    int rowbase = by * 8;
#pragma unroll 4
    for (int it = 0; it < 512; it++) {
        int e = it * 128 + t;
        int x = e & 63, row = (e >> 6) & 7, co = e >> 9;
        int gi = ((n * 128 + co) * 64 + rowbase + row) * 64 + x;
        float v = __ldg(xin + gi)
                + sw2[co * 2]     * h_s[0][row][x]
                + sw2[co * 2 + 1] * h_s[1][row][x];
        xout[gi] = v;
    }
}

// ---------------- vector quantizer -------------------------------------------
// block = 64 pixels (fixed n,y). 512 codes, D=64.
__global__ void __launch_bounds__(256) vq_kernel(
    const float* __restrict__ ze, const float* __restrict__ cb,
    float* __restrict__ zq, float* __restrict__ partials)
{
    __shared__ __align__(16) float f_s[64 * 64];    // [d][x]
    __shared__ __align__(16) float cb_s[64 * 68];   // [d][code] padded
    __shared__ float norm_s[512];
    __shared__ int   idx_s[64];
    __shared__ float red_s[64];

    int t = threadIdx.x;
    int b = blockIdx.x;
    int n = b >> 6, y = b & 63;

    for (int i = t; i < 4096; i += 256) {
        int d = i >> 6, x = i & 63;
        f_s[i] = ze[((n * 64 + d) * 64 + y) * 64 + x];
    }
    for (int c = t; c < 512; c += 256) {
        float s = 0.f;
        const float* cp = cb + c * 64;
#pragma unroll 8
        for (int d = 0; d < 64; d++) { float v = __ldg(cp + d); s = fmaf(v, v, s); }
        norm_s[c] = s;
    }
    __syncthreads();

    int cxT = t & 15, pyT = t >> 4;
    float best[4] = {3.4e38f, 3.4e38f, 3.4e38f, 3.4e38f};
    int   bidx[4] = {0, 0, 0, 0};

    for (int ch = 0; ch < 8; ch++) {
        __syncthreads();
        for (int i = t; i < 4096; i += 256) {
            int d = i & 63, c = i >> 6;
            cb_s[d * 68 + c] = __ldg(&cb[(ch * 64 + c) * 64 + d]);
        }
        __syncthreads();

        float dot[4][4];
#pragma unroll
        for (int pp = 0; pp < 4; pp++)
#pragma unroll
            for (int cc = 0; cc < 4; cc++) dot[pp][cc] = 0.f;

        for (int d = 0; d < 64; d++) {
            float4 fv4 = *(const float4*)&f_s[d * 64 + pyT * 4];
            float4 cv4 = *(const float4*)&cb_s[d * 68 + cxT * 4];
            float fv[4] = {fv4.x, fv4.y, fv4.z, fv4.w};
            float cv[4] = {cv4.x, cv4.y, cv4.z, cv4.w};
#pragma unroll
            for (int pp = 0; pp < 4; pp++)
#pragma unroll
                for (int cc = 0; cc < 4; cc++)
                    dot[pp][cc] = fmaf(fv[pp], cv[cc], dot[pp][cc]);
        }
#pragma unroll
        for (int cc = 0; cc < 4; cc++) {
            int code = ch * 64 + cxT * 4 + cc;
            float nrm = norm_s[code];
#pragma unroll
            for (int pp = 0; pp < 4; pp++) {
                float dist = fmaf(-2.f, dot[pp][cc], nrm);
                if (dist < best[pp]) { best[pp] = dist; bidx[pp] = code; }
            }
        }
    }

    for (int off = 1; off < 16; off <<= 1) {
#pragma unroll
        for (int pp = 0; pp < 4; pp++) {
            float ob = __shfl_xor_sync(0xffffffffu, best[pp], off);
            int   oi = __shfl_xor_sync(0xffffffffu, bidx[pp], off);
            if (ob < best[pp] || (ob == best[pp] && oi < bidx[pp])) {
                best[pp] = ob; bidx[pp] = oi;
            }
        }
    }
    if (cxT == 0)
#pragma unroll
        for (int pp = 0; pp < 4; pp++) idx_s[pyT * 4 + pp] = bidx[pp];
    __syncthreads();

    // z_q write (NCHW)
    for (int i = t; i < 4096; i += 256) {
        int d = i >> 6, x = i & 63;
        zq[((n * 64 + d) * 64 + y) * 64 + x] = __ldg(&cb[idx_s[x] * 64 + d]);
    }

    // loss partial: exact squared distance per pixel
    if (t < 64) {
        int id = idx_s[t];
        const float* cp = cb + id * 64;
        float s = 0.f;
#pragma unroll 8
        for (int d = 0; d < 64; d++) {
            float diff = __ldg(cp + d) - f_s[d * 64 + t];
            s = fmaf(diff, diff, s);
        }
        red_s[t] = s;
    }
    __syncthreads();
    if (t == 0) {
        float s = 0.f;
        for (int i = 0; i < 64; i++) s += red_s[i];
        partials[b] = s;
    }
}

__global__ void __launch_bounds__(256) finalize_loss(
    const float* __restrict__ partials, float* __restrict__ dst)
{
    __shared__ float s[256];
    int t = threadIdx.x;
    float v = 0.f;
    for (int i = t; i < 1024; i += 256) v += partials[i];
    s[t] = v;
    __syncthreads();
    for (int off = 128; off > 0; off >>= 1) {
        if (t < off) s[t] += s[t + off];
        __syncthreads();
    }
    if (t == 0) dst[0] = 1.25f * s[0] / 4194304.f;  // (1 + BETA) * MSE
}

// ---------------- host launcher ----------------------------------------------
extern "C" void kernel_launch(void* const* d_in, const int* in_sizes, int n_in,
                              void* d_out, int out_size)
{
    (void)in_sizes; (void)n_in; (void)out_size;
    const float* x       = (const float*)d_in[0];
    const float* enc_w1  = (const float*)d_in[1];
    const float* enc_b1  = (const float*)d_in[2];
    const float* enc_w2  = (const float*)d_in[3];
    const float* enc_b2  = (const float*)d_in[4];
    const float* enc_w3  = (const float*)d_in[5];
    const float* enc_b3  = (const float*)d_in[6];
    const float* enc_rw1 = (const float*)d_in[7];
    const float* enc_rw2 = (const float*)d_in[8];
    const float* pre_w   = (const float*)d_in[9];
    const float* pre_b   = (const float*)d_in[10];
    const float* cb      = (const float*)d_in[11];
    const float* dec_wt1 = (const float*)d_in[12];
    const float* dec_bt1 = (const float*)d_in[13];
    const float* dec_rw1 = (const float*)d_in[14];
    const float* dec_rw2 = (const float*)d_in[15];
    const float* dec_wt2 = (const float*)d_in[16];
    const float* dec_bt2 = (const float*)d_in[17];
    const float* dec_wt3 = (const float*)d_in[18];
    const float* dec_bt3 = (const float*)d_in[19];
    float* out = (float*)d_out;

    float *pA, *pB, *pB2, *pC, *pD, *pE, *pF, *pPart;
    cudaGetSymbolAddress((void**)&pA,  g_A);
    cudaGetSymbolAddress((void**)&pB,  g_B);
    cudaGetSymbolAddress((void**)&pB2, g_B2);
    cudaGetSymbolAddress((void**)&pC,  g_C);
    cudaGetSymbolAddress((void**)&pD,  g_D);
    cudaGetSymbolAddress((void**)&pE,  g_E);
    cudaGetSymbolAddress((void**)&pF,  g_F);
    cudaGetSymbolAddress((void**)&pPart, g_part);

    // encoder
    conv_fwd<4,2,false,false><<<dim3(2,16,16*8), 128>>>(
        x, enc_w1, enc_b1, nullptr, pA, 3, 64, 256, 256, 128, 128, 1, 8, 1);
    conv_fwd<4,2,false,false><<<dim3(1,8,16*16), 128>>>(
        pA, enc_w2, enc_b2, nullptr, pB, 64, 128, 128, 128, 64, 64, 1, 16, 1);
    conv_fwd<3,1,false,false><<<dim3(1,8,16*16), 128>>>(
        pB, enc_w3, enc_b3, nullptr, pC, 128, 128, 64, 64, 64, 64, 1, 16, 0);
    for (int i = 0; i < 2; i++) {
        conv_fwd<3,1,true,false><<<dim3(1,8,16*4), 128>>>(
            pC, enc_rw1, nullptr, nullptr, pD, 128, 32, 64, 64, 64, 64, 1, 4, 1);
        conv_fwd<1,1,false,false><<<dim3(1,8,16*16), 128>>>(
            pD, enc_rw2, nullptr, pC, pC, 32, 128, 64, 64, 64, 64, 0, 16, 0);
    }
    conv_fwd<1,1,true,false><<<dim3(1,8,16*8), 128>>>(
        pC, pre_w, pre_b, nullptr, pE, 128, 64, 64, 64, 64, 64, 0, 8, 0);

    // quantizer
    vq_kernel<<<1024, 256>>>(pE, cb, pF, pPart);
    finalize_loss<<<1, 256>>>(pPart, out + 3145728);

    // decoder
    conv_fwd<3,1,false,true><<<dim3(1,8,16*16), 128>>>(
        pF, dec_wt1, dec_bt1, nullptr, pB, 64, 128, 64, 64, 64, 64, 1, 16, 0);
    for (int i = 0; i < 32; i++) {
        const float* src = (i & 1) ? pB2 : pB;
        float*       dst = (i & 1) ? pB  : pB2;
        decres_fused<<<dim3(8,16), 128>>>(src, dec_rw1, dec_rw2, dst);
    }
    // after 32 iters result is back in pB
    convt_s2<<<dim3(2,16,16*8), 128>>>(
        pB, dec_wt2, dec_bt2, pA, 128, 64, 64, 64, 8, 1, 1);
    convt_s2<<<dim3(4,32,16*1), 128>>>(
        pA, dec_wt3, dec_bt3, out, 64, 3, 128, 128, 1, 0, 0);
}

// round 6
// speedup vs baseline: 1.8550x; 1.8550x over previous
#include <cuda_runtime.h>
#include <math.h>

typedef unsigned long long u64;

__device__ __forceinline__ u64 pk2(float v) {
    u64 r; asm("mov.b64 %0, {%1,%1};" : "=l"(r) : "f"(v)); return r;
}
__device__ __forceinline__ void fma2(u64& d, u64 a, u64 b) {
    asm("fma.rn.f32x2 %0, %1, %2, %0;" : "+l"(d) : "l"(a), "l"(b));
}
__device__ __forceinline__ float2 upk(u64 v) {
    float2 r; asm("mov.b64 {%0,%1}, %2;" : "=f"(r.x), "=f"(r.y) : "l"(v)); return r;
}
__device__ __forceinline__ u64 add2(u64 a, u64 b) {
    u64 r; asm("add.rn.f32x2 %0, %1, %2;" : "=l"(r) : "l"(a), "l"(b)); return r;
}

// ---------------- scratch (device globals: allocation-free) ------------------
__device__ float g_A [16*64*128*128];   // 67 MB
__device__ float g_B [16*128*64*64];    // 33.5 MB
__device__ float g_B2[16*128*64*64];    // 33.5 MB
__device__ float g_C [16*128*64*64];    // 33.5 MB
__device__ float g_D [16*32*64*64];     // 8.4 MB
__device__ float g_E [16*64*64*64];     // 16.8 MB (z_e)
__device__ float g_F [16*64*64*64];     // 16.8 MB (z_q)
__device__ float g_part[1024];

// ---------------- generic direct conv (f32x2, sliding window) -----------------
// thread: 4 out-x x 8 out-channels (4 c-pairs). block 128 = 16 px-grp x 8 rows.
// smem weights: [(ci*KK + kk)*8 + c]  -> channel-pair via single LDS.64
template<int K, int STRIDE, bool RELU_IN, bool TRANSPOSED>
__global__ void __launch_bounds__(128) conv_fwd(
    const float* __restrict__ in, const float* __restrict__ w,
    const float* __restrict__ bias, const float* __restrict__ resid,
    float* __restrict__ out,
    int CIN, int COUT, int H, int W, int OH, int OW, int PAD, int cgroups,
    int relu_out)
{
    constexpr int KK = K * K;
    constexpr int CICH = (K == 4) ? 64 : 128;
    constexpr int SPAN = 3 * STRIDE + K;   // input window per ky
    __shared__ __align__(16) float sw[CICH * KK * 8];

    int t   = threadIdx.x;
    int tx  = t & 15, ty = t >> 4;
    int ox0 = blockIdx.x * 64 + tx * 4;
    int oy  = blockIdx.y * 8 + ty;
    int n   = blockIdx.z / cgroups;
    int co0 = (blockIdx.z % cgroups) * 8;
    int ixbase = ox0 * STRIDE - PAD;

    u64 acc2[4][4];
#pragma unroll
    for (int cp = 0; cp < 4; cp++)
#pragma unroll
        for (int p = 0; p < 4; p++) acc2[cp][p] = 0ull;

    for (int ci0 = 0; ci0 < CIN; ci0 += CICH) {
        int cich = min(CICH, CIN - ci0);
        int nw = cich * KK * 8;
        __syncthreads();
        for (int i = t; i < nw; i += 128) {
            int c  = i & 7;
            int r  = i >> 3;            // ci*KK + kk
            int ci = r / KK;
            int kk = r - ci * KK;
            int ky = kk / K, kx = kk - ky * K;
            int co = co0 + c;
            float v = 0.f;
            if (co < COUT) {
                if (TRANSPOSED)
                    v = w[(((ci0 + ci) * COUT + co) * K + (K - 1 - ky)) * K + (K - 1 - kx)];
                else
                    v = w[((co * CIN + (ci0 + ci)) * K + ky) * K + kx];
            }
            sw[i] = v;
        }
        __syncthreads();

        const float* inb = in + (n * CIN + ci0) * H * W;
        for (int ci = 0; ci < cich; ci++) {
            const float* inc = inb + ci * H * W;
            const float* wci = sw + ci * KK * 8;
#pragma unroll
            for (int ky = 0; ky < K; ky++) {
                int iy = oy * STRIDE - PAD + ky;
                if ((unsigned)iy >= (unsigned)H) continue;
                const float* rowp = inc + iy * W + ixbase;
                u64 ivs[SPAN];
#pragma unroll
                for (int q = 0; q < SPAN; q++) {
                    int ix = ixbase + q;
                    float v = ((unsigned)ix < (unsigned)W) ? __ldg(rowp + q) : 0.f;
                    if (RELU_IN) v = fmaxf(v, 0.f);
                    ivs[q] = pk2(v);
                }
#pragma unroll
                for (int kx = 0; kx < K; kx++) {
                    const float* wp = wci + (ky * K + kx) * 8;
#pragma unroll
                    for (int cp = 0; cp < 4; cp++) {
                        u64 wv2 = *(const u64*)(wp + cp * 2);
#pragma unroll
                        for (int p = 0; p < 4; p++)
                            fma2(acc2[cp][p], ivs[p * STRIDE + kx], wv2);
                    }
                }
            }
        }
    }

#pragma unroll
    for (int cp = 0; cp < 4; cp++) {
        float2 v[4];
#pragma unroll
        for (int p = 0; p < 4; p++) v[p] = upk(acc2[cp][p]);
#pragma unroll
        for (int h2 = 0; h2 < 2; h2++) {
            int co = co0 + cp * 2 + h2;
            if (co >= COUT) continue;
            float b = bias ? __ldg(bias + co) : 0.f;
            int ob = ((n * COUT + co) * OH + oy) * OW + ox0;
#pragma unroll
            for (int p = 0; p < 4; p++) {
                float val = (h2 ? v[p].y : v[p].x) + b;
                if (resid) val += resid[ob + p];
                if (relu_out) val = fmaxf(val, 0.f);
                out[ob + p] = val;
            }
        }
    }
}

// ---------------- transposed conv, stride 2, K=4, pad 1 (f32x2) ---------------
// gather form, parity-direct taps. weight [ci][co][ky][kx] (unflipped).
__global__ void __launch_bounds__(128) convt_s2(
    const float* __restrict__ in, const float* __restrict__ w,
    const float* __restrict__ bias, float* __restrict__ out,
    int CIN, int COUT, int H, int W, int cgroups, int relu_in, int relu_out)
{
    __shared__ __align__(16) float sw[64 * 16 * 8];  // [(ci*16+kk)*8 + c]
    int t = threadIdx.x;
    int tx = t & 15, tyv = t >> 4;
    int parity = blockIdx.x & 1;
    int xch    = blockIdx.x >> 1;
    int OH = 2 * H, OW = 2 * W;
    int ox0 = xch * 128 + 8 * tx + parity;   // outputs ox0 + 2p
    int oy  = blockIdx.y * 8 + tyv;
    int n   = blockIdx.z / cgroups;
    int co0 = (blockIdx.z % cgroups) * 8;

    int kyp = (oy + 1) & 1;        // valid ky: kyp, kyp+2
    int kxp = (ox0 + 1) & 1;       // valid kx: kxp, kxp+2
    int ixw = ((ox0 + 1 - kxp) >> 1) - 1;  // window start (5 floats)

    u64 acc2[4][4];
#pragma unroll
    for (int cp = 0; cp < 4; cp++)
#pragma unroll
        for (int p = 0; p < 4; p++) acc2[cp][p] = 0ull;

    for (int ci0 = 0; ci0 < CIN; ci0 += 64) {
        int cich = min(64, CIN - ci0);
        int nw = cich * 16 * 8;
        __syncthreads();
        for (int i = t; i < nw; i += 128) {
            int c  = i & 7;
            int r  = i >> 3;
            int ci = r >> 4;
            int kk = r & 15;
            int co = co0 + c;
            sw[i] = (co < COUT) ? w[((ci0 + ci) * COUT + co) * 16 + kk] : 0.f;
        }
        __syncthreads();

        for (int ci = 0; ci < cich; ci++) {
            const float* inc = in + (n * CIN + ci0 + ci) * H * W;
            const float* wci = sw + ci * 16 * 8;
#pragma unroll
            for (int ky2 = 0; ky2 < 2; ky2++) {
                int ky = kyp + 2 * ky2;
                int iy = (oy + 1 - ky) >> 1;
                if ((unsigned)iy >= (unsigned)H) continue;
                const float* rowp = inc + iy * W + ixw;
                u64 ivs[5];
#pragma unroll
                for (int q = 0; q < 5; q++) {
                    int ix = ixw + q;
                    float v = ((unsigned)ix < (unsigned)W) ? __ldg(rowp + q) : 0.f;
                    if (relu_in) v = fmaxf(v, 0.f);
                    ivs[q] = pk2(v);
                }
#pragma unroll
                for (int kx2 = 0; kx2 < 2; kx2++) {
                    int kx  = kxp + 2 * kx2;
                    int ofs = 1 - kx2;
                    const float* wp = wci + (ky * 4 + kx) * 8;
#pragma unroll
                    for (int cp = 0; cp < 4; cp++) {
                        u64 wv2 = *(const u64*)(wp + cp * 2);
#pragma unroll
                        for (int p = 0; p < 4; p++)
                            fma2(acc2[cp][p], ivs[ofs + p], wv2);
                    }
                }
            }
        }
    }

#pragma unroll
    for (int cp = 0; cp < 4; cp++) {
        float2 v[4];
#pragma unroll
        for (int p = 0; p < 4; p++) v[p] = upk(acc2[cp][p]);
#pragma unroll
        for (int h2 = 0; h2 < 2; h2++) {
            int co = co0 + cp * 2 + h2;
            if (co >= COUT) continue;
            float b = bias ? __ldg(bias + co) : 0.f;
#pragma unroll
            for (int p = 0; p < 4; p++) {
                int ox = ox0 + 2 * p;
                int o = ((n * COUT + co) * OH + oy) * OW + ox;
                float val = (h2 ? v[p].y : v[p].x) + b;
                if (relu_out) val = fmaxf(val, 0.f);
                out[o] = val;
            }
        }
    }
}

// ---------------- fused decoder residual iteration (v2) -----------------------
// x_out = x_in + W2 * relu(W1 (*) relu(x_in)), W1:[2,128,3,3], W2:[128,2,1,1]
// 256 threads: ci split across halves in phase1; float4 phase2.
__global__ void __launch_bounds__(256) decres_fused(
    const float* __restrict__ xin, const float* __restrict__ w1,
    const float* __restrict__ w2, float* __restrict__ xout)
{
    __shared__ __align__(8) float sw1[2304];     // [(ci*9+k)*2 + ch]
    __shared__ float sw2[256];
    __shared__ u64  part[1024];                  // [half][wg][p]
    __shared__ __align__(16) float h_s[2][8][64];

    int t    = threadIdx.x;
    int half = t >> 7, wg = t & 127;
    int by = blockIdx.x;            // 0..7 (8-row stripe)
    int n  = blockIdx.y;            // 0..15
    for (int i = t; i < 2304; i += 256) {
        int ch = i & 1, r = i >> 1;              // r = ci*9+k
        sw1[i] = w1[ch * 1152 + r];
    }
    if (t < 256) sw2[t] = w2[t];
    __syncthreads();

    int tx = wg & 15, tyv = wg >> 4;
    int ox0 = tx * 4;
    int oy  = by * 8 + tyv;
    u64 a2[4] = {0ull, 0ull, 0ull, 0ull};
    const float* xb = xin + (n * 128 + half * 64) * 4096;
    for (int ci = 0; ci < 64; ci++) {
        const float* inc = xb + ci * 4096;
        const float* wci = sw1 + (half * 64 + ci) * 18;
#pragma unroll
        for (int ky = 0; ky < 3; ky++) {
            int iy = oy - 1 + ky;
            if ((unsigned)iy >= 64u) continue;
            const float* rowp = inc + iy * 64 + ox0 - 1;
            u64 ivs[6];
#pragma unroll
            for (int q = 0; q < 6; q++) {
                int ix = ox0 - 1 + q;
                float v = ((unsigned)ix < 64u) ? __ldg(rowp + q) : 0.f;
                ivs[q] = pk2(fmaxf(v, 0.f));
            }
#pragma unroll
            for (int kx = 0; kx < 3; kx++) {
                u64 wv2 = *(const u64*)(wci + (ky * 3 + kx) * 2);
#pragma unroll
                for (int p = 0; p < 4; p++)
                    fma2(a2[p], ivs[p + kx], wv2);
            }
        }
    }
#pragma unroll
    for (int p = 0; p < 4; p++) part[(half * 128 + wg) * 4 + p] = a2[p];
    __syncthreads();

    // combine halves -> h (relu)
    for (int i = t; i < 512; i += 256) {
        u64 s = add2(part[i], part[512 + i]);
        float2 v = upk(s);
        int wi = i >> 2, p = i & 3;
        int row = wi >> 4, x = (wi & 15) * 4 + p;
        h_s[0][row][x] = fmaxf(v.x, 0.f);
        h_s[1][row][x] = fmaxf(v.y, 0.f);
    }
    __syncthreads();

    // phase 2: x + W2*h, float4
    int rowbase = by * 8;
    const float4* xin4 = (const float4*)xin;
    float4* xout4 = (float4*)xout;
#pragma unroll 4
    for (int it = 0; it < 64; it++) {
        int e = it * 256 + t;
        int x4 = e & 15, row = (e >> 4) & 7, co = e >> 7;
        int gi = ((n * 128 + co) * 64 + rowbase + row) * 16 + x4;
        float4 v = xin4[gi];
        float w0 = sw2[co * 2], w1v = sw2[co * 2 + 1];
        const float* h0 = &h_s[0][row][x4 * 4];
        const float* h1 = &h_s[1][row][x4 * 4];
        v.x += w0 * h0[0] + w1v * h1[0];
        v.y += w0 * h0[1] + w1v * h1[1];
        v.z += w0 * h0[2] + w1v * h1[2];
        v.w += w0 * h0[3] + w1v * h1[3];
        xout4[gi] = v;
    }
}

// ---------------- vector quantizer -------------------------------------------
__global__ void __launch_bounds__(256) vq_kernel(
    const float* __restrict__ ze, const float* __restrict__ cb,
    float* __restrict__ zq, float* __restrict__ partials)
{
    __shared__ __align__(16) float f_s[64 * 64];    // [d][x]
    __shared__ __align__(16) float cb_s[64 * 68];   // [d][code] padded
    __shared__ float norm_s[512];
    __shared__ int   idx_s[64];
    __shared__ float red_s[64];

    int t = threadIdx.x;
    int b = blockIdx.x;
    int n = b >> 6, y = b & 63;

    for (int i = t; i < 4096; i += 256) {
        int d = i >> 6, x = i & 63;
        f_s[i] = ze[((n * 64 + d) * 64 + y) * 64 + x];
    }
    for (int c = t; c < 512; c += 256) {
        float s = 0.f;
        const float* cp = cb + c * 64;
#pragma unroll 8
        for (int d = 0; d < 64; d++) { float v = __ldg(cp + d); s = fmaf(v, v, s); }
        norm_s[c] = s;
    }
    __syncthreads();

    int cxT = t & 15, pyT = t >> 4;
    float best[4] = {3.4e38f, 3.4e38f, 3.4e38f, 3.4e38f};
    int   bidx[4] = {0, 0, 0, 0};

    for (int ch = 0; ch < 8; ch++) {
        __syncthreads();
        for (int i = t; i < 4096; i += 256) {
            int d = i & 63, c = i >> 6;
            cb_s[d * 68 + c] = __ldg(&cb[(ch * 64 + c) * 64 + d]);
        }
        __syncthreads();

        float dot[4][4];
#pragma unroll
        for (int pp = 0; pp < 4; pp++)
#pragma unroll
            for (int cc = 0; cc < 4; cc++) dot[pp][cc] = 0.f;

        for (int d = 0; d < 64; d++) {
            float4 fv4 = *(const float4*)&f_s[d * 64 + pyT * 4];
            float4 cv4 = *(const float4*)&cb_s[d * 68 + cxT * 4];
            float fv[4] = {fv4.x, fv4.y, fv4.z, fv4.w};
            float cv[4] = {cv4.x, cv4.y, cv4.z, cv4.w};
#pragma unroll
            for (int pp = 0; pp < 4; pp++)
#pragma unroll
                for (int cc = 0; cc < 4; cc++)
                    dot[pp][cc] = fmaf(fv[pp], cv[cc], dot[pp][cc]);
        }
#pragma unroll
        for (int cc = 0; cc < 4; cc++) {
            int code = ch * 64 + cxT * 4 + cc;
            float nrm = norm_s[code];
#pragma unroll
            for (int pp = 0; pp < 4; pp++) {
                float dist = fmaf(-2.f, dot[pp][cc], nrm);
                if (dist < best[pp]) { best[pp] = dist; bidx[pp] = code; }
            }
        }
    }

    for (int off = 1; off < 16; off <<= 1) {
#pragma unroll
        for (int pp = 0; pp < 4; pp++) {
            float ob = __shfl_xor_sync(0xffffffffu, best[pp], off);
            int   oi = __shfl_xor_sync(0xffffffffu, bidx[pp], off);
            if (ob < best[pp] || (ob == best[pp] && oi < bidx[pp])) {
                best[pp] = ob; bidx[pp] = oi;
            }
        }
    }
    if (cxT == 0)
#pragma unroll
        for (int pp = 0; pp < 4; pp++) idx_s[pyT * 4 + pp] = bidx[pp];
    __syncthreads();

    for (int i = t; i < 4096; i += 256) {
        int d = i >> 6, x = i & 63;
        zq[((n * 64 + d) * 64 + y) * 64 + x] = __ldg(&cb[idx_s[x] * 64 + d]);
    }

    if (t < 64) {
        int id = idx_s[t];
        const float* cp = cb + id * 64;
        float s = 0.f;
#pragma unroll 8
        for (int d = 0; d < 64; d++) {
            float diff = __ldg(cp + d) - f_s[d * 64 + t];
            s = fmaf(diff, diff, s);
        }
        red_s[t] = s;
    }
    __syncthreads();
    if (t == 0) {
        float s = 0.f;
        for (int i = 0; i < 64; i++) s += red_s[i];
        partials[b] = s;
    }
}

__global__ void __launch_bounds__(256) finalize_loss(
    const float* __restrict__ partials, float* __restrict__ dst)
{
    __shared__ float s[256];
    int t = threadIdx.x;
    float v = 0.f;
    for (int i = t; i < 1024; i += 256) v += partials[i];
    s[t] = v;
    __syncthreads();
    for (int off = 128; off > 0; off >>= 1) {
        if (t < off) s[t] += s[t + off];
        __syncthreads();
    }
    if (t == 0) dst[0] = 1.25f * s[0] / 4194304.f;  // (1 + BETA) * MSE
}

// ---------------- host launcher ----------------------------------------------
extern "C" void kernel_launch(void* const* d_in, const int* in_sizes, int n_in,
                              void* d_out, int out_size)
{
    (void)in_sizes; (void)n_in; (void)out_size;
    const float* x       = (const float*)d_in[0];
    const float* enc_w1  = (const float*)d_in[1];
    const float* enc_b1  = (const float*)d_in[2];
    const float* enc_w2  = (const float*)d_in[3];
    const float* enc_b2  = (const float*)d_in[4];
    const float* enc_w3  = (const float*)d_in[5];
    const float* enc_b3  = (const float*)d_in[6];
    const float* enc_rw1 = (const float*)d_in[7];
    const float* enc_rw2 = (const float*)d_in[8];
    const float* pre_w   = (const float*)d_in[9];
    const float* pre_b   = (const float*)d_in[10];
    const float* cb      = (const float*)d_in[11];
    const float* dec_wt1 = (const float*)d_in[12];
    const float* dec_bt1 = (const float*)d_in[13];
    const float* dec_rw1 = (const float*)d_in[14];
    const float* dec_rw2 = (const float*)d_in[15];
    const float* dec_wt2 = (const float*)d_in[16];
    const float* dec_bt2 = (const float*)d_in[17];
    const float* dec_wt3 = (const float*)d_in[18];
    const float* dec_bt3 = (const float*)d_in[19];
    float* out = (float*)d_out;

    float *pA, *pB, *pB2, *pC, *pD, *pE, *pF, *pPart;
    cudaGetSymbolAddress((void**)&pA,  g_A);
    cudaGetSymbolAddress((void**)&pB,  g_B);
    cudaGetSymbolAddress((void**)&pB2, g_B2);
    cudaGetSymbolAddress((void**)&pC,  g_C);
    cudaGetSymbolAddress((void**)&pD,  g_D);
    cudaGetSymbolAddress((void**)&pE,  g_E);
    cudaGetSymbolAddress((void**)&pF,  g_F);
    cudaGetSymbolAddress((void**)&pPart, g_part);

    // encoder
    conv_fwd<4,2,false,false><<<dim3(2,16,16*8), 128>>>(
        x, enc_w1, enc_b1, nullptr, pA, 3, 64, 256, 256, 128, 128, 1, 8, 1);
    conv_fwd<4,2,false,false><<<dim3(1,8,16*16), 128>>>(
        pA, enc_w2, enc_b2, nullptr, pB, 64, 128, 128, 128, 64, 64, 1, 16, 1);
    conv_fwd<3,1,false,false><<<dim3(1,8,16*16), 128>>>(
        pB, enc_w3, enc_b3, nullptr, pC, 128, 128, 64, 64, 64, 64, 1, 16, 0);
    for (int i = 0; i < 2; i++) {
        conv_fwd<3,1,true,false><<<dim3(1,8,16*4), 128>>>(
            pC, enc_rw1, nullptr, nullptr, pD, 128, 32, 64, 64, 64, 64, 1, 4, 1);
        conv_fwd<1,1,false,false><<<dim3(1,8,16*16), 128>>>(
            pD, enc_rw2, nullptr, pC, pC, 32, 128, 64, 64, 64, 64, 0, 16, 0);
    }
    conv_fwd<1,1,true,false><<<dim3(1,8,16*8), 128>>>(
        pC, pre_w, pre_b, nullptr, pE, 128, 64, 64, 64, 64, 64, 0, 8, 0);

    // quantizer
    vq_kernel<<<1024, 256>>>(pE, cb, pF, pPart);
    finalize_loss<<<1, 256>>>(pPart, out + 3145728);

    // decoder
    conv_fwd<3,1,false,true><<<dim3(1,8,16*16), 128>>>(
        pF, dec_wt1, dec_bt1, nullptr, pB, 64, 128, 64, 64, 64, 64, 1, 16, 0);
    for (int i = 0; i < 32; i++) {
        const float* src = (i & 1) ? pB2 : pB;
        float*       dst = (i & 1) ? pB  : pB2;
        decres_fused<<<dim3(8,16), 256>>>(src, dec_rw1, dec_rw2, dst);
    }
    // after 32 iters result is back in pB
    convt_s2<<<dim3(2,16,16*8), 128>>>(
        pB, dec_wt2, dec_bt2, pA, 128, 64, 64, 64, 8, 1, 1);
    convt_s2<<<dim3(4,32,16*1), 128>>>(
        pA, dec_wt3, dec_bt3, out, 64, 3, 128, 128, 1, 0, 0);
}